// round 1
// baseline (speedup 1.0000x reference)
#include <cuda_runtime.h>

// Problem: x [8,3,256,256] f32 in [0,1]; bin_vals [64] f32 (linspace -1..1).
// out [8,3,64] f32: hist[nc][b] = sum_p exp(-( (2x-1) - bin_b )^2 / (2*0.02^2)),
// normalized per nc by (sum_b hist + 1e-8).
//
// Strategy: transpose/gather. Each thread owns one bin (register accumulator),
// pixels are staged in SMEM and broadcast to all 64 bin-threads of a group.
// No atomics in the hot loop; MUFU(EX2)-bound by design (~100M exps total).

#define NC_TOTAL   24          // 8*3
#define PIX_PER_NC 65536       // 256*256
#define HB         64
#define SPLITS     64          // blocks per (n,c)
#define CHUNK      1024        // pixels per block (PIX_PER_NC / SPLITS)
#define KCOEF      1250.0f     // 1/(2*sigma^2), sigma=0.02

__device__ float g_hist[NC_TOTAL * HB];   // unnormalized scratch, zeroed each run

__global__ void zero_hist_kernel() {
    int i = blockIdx.x * blockDim.x + threadIdx.x;
    if (i < NC_TOTAL * HB) g_hist[i] = 0.0f;
}

__global__ __launch_bounds__(256) void hist_acc_kernel(
    const float* __restrict__ x, const float* __restrict__ bin_vals)
{
    const int nc    = blockIdx.y;
    const int split = blockIdx.x;
    const int tid   = threadIdx.x;
    const int bin   = tid & (HB - 1);
    const int grp   = tid >> 6;          // 0..3

    __shared__ float4 sx[CHUNK / 4];     // 256 float4 = 1024 pixels (4KB)
    __shared__ float  racc[256];

    // Cooperative coalesced tile load: 256 threads x float4 = 1024 floats.
    const float4* xp = reinterpret_cast<const float4*>(
        x + (size_t)nc * PIX_PER_NC + (size_t)split * CHUNK);
    sx[tid] = xp[tid];

    const float b = bin_vals[bin];
    const float c = -1.0f - b;           // d = 2*v - 1 - b = fma(v, 2, c)
    float acc = 0.0f;

    __syncthreads();

    // Group grp processes pixels [grp*256, grp*256+256) across all 64 bins.
    const float4* base = sx + grp * 64;  // 64 float4 = 256 pixels
#pragma unroll 8
    for (int i = 0; i < 64; ++i) {
        float4 v = base[i];              // uniform address within group -> LDS broadcast
        float d0 = fmaf(v.x, 2.0f, c);
        float d1 = fmaf(v.y, 2.0f, c);
        float d2 = fmaf(v.z, 2.0f, c);
        float d3 = fmaf(v.w, 2.0f, c);
        acc += __expf(-KCOEF * d0 * d0);
        acc += __expf(-KCOEF * d1 * d1);
        acc += __expf(-KCOEF * d2 * d2);
        acc += __expf(-KCOEF * d3 * d3);
    }

    racc[tid] = acc;
    __syncthreads();
    if (tid < HB) {
        float s = racc[tid] + racc[tid + 64] + racc[tid + 128] + racc[tid + 192];
        atomicAdd(&g_hist[nc * HB + tid], s);
    }
}

__global__ void finalize_kernel(float* __restrict__ out) {
    const int nc = blockIdx.x;
    const int t  = threadIdx.x;          // 0..63
    float v = g_hist[nc * HB + t];

    // Sum 64 values across 2 warps.
    float s = v;
#pragma unroll
    for (int o = 16; o; o >>= 1) s += __shfl_xor_sync(0xffffffffu, s, o);
    __shared__ float ws[2];
    if ((t & 31) == 0) ws[t >> 5] = s;
    __syncthreads();
    float tot = ws[0] + ws[1];

    out[nc * HB + t] = v / (tot + 1e-8f);
}

extern "C" void kernel_launch(void* const* d_in, const int* in_sizes, int n_in,
                              void* d_out, int out_size) {
    const float* x        = (const float*)d_in[0];   // [8,3,256,256]
    const float* bin_vals = (const float*)d_in[1];   // [64]
    float* out            = (float*)d_out;           // [8,3,64]

    zero_hist_kernel<<<6, 256>>>();

    dim3 grid(SPLITS, NC_TOTAL);
    hist_acc_kernel<<<grid, 256>>>(x, bin_vals);

    finalize_kernel<<<NC_TOTAL, HB>>>(out);
}

// round 2
// speedup vs baseline: 1.5165x; 1.5165x over previous
#include <cuda_runtime.h>

// RGBuvHistBlock: x [8,3,256,256] f32 in [0,1]; bin_vals [64] = linspace(-1,1).
// hist[nc][b] = sum_p exp(-((2x-1)-b)^2 / (2*0.02^2)), normalized per nc.
//
// Single fused kernel. Gather form: thread owns a bin, pixels broadcast from
// SMEM. Values pre-scaled so the inner op is d=s-t; arg=-d*d; ex2.approx;
// acc+=  -> MUFU(EX2)-bound at 8 cyc/SMSP per 32 pixel-bins.
// 3.146M warp-EX2 / 592 SMSPs * 8cyc ~= 42.5k cyc ~= 22us floor.

#define NC_TOTAL   24
#define PIX_PER_NC 65536
#define HB         64
#define SPLITS     64
#define CHUNK      1024          // pixels per block
#define GROUPS     2             // 128 threads = 2 groups of 64 bins
#define PPG        (CHUNK / GROUPS)   // 512 pixels per group

// scale so weight = 2^(-(s - t_b)^2):  s = sqrt(k*log2e)*(2v-1)
// k = 1/(2*sigma^2) = 1250;  k*log2e = 1803.3688011112043; sqrt = 42.466089...
#define SA   42.46608994f
#define SA2  84.93217988f        // 2*SA

__device__ float    g_part[NC_TOTAL * SPLITS * HB];  // per-block partials
__device__ unsigned g_cnt[NC_TOTAL];                 // arrival counters (self-resetting)

__device__ __forceinline__ float ex2f(float a) {
    float r;
    asm("ex2.approx.ftz.f32 %0, %1;" : "=f"(r) : "f"(a));
    return r;
}

__global__ __launch_bounds__(128) void hist_fused_kernel(
    const float* __restrict__ x, const float* __restrict__ bin_vals,
    float* __restrict__ out)
{
    const int nc    = blockIdx.y;
    const int split = blockIdx.x;
    const int tid   = threadIdx.x;
    const int bin   = tid & (HB - 1);
    const int grp   = tid >> 6;                    // 0..1

    __shared__ float4 sx[CHUNK / 4];               // 256 float4 (4 KB), pre-scaled s
    __shared__ float  racc[128];
    __shared__ float  ws[2];
    __shared__ int    slast;

    // Stage + prescale: s = fma(v, 2*SA, -SA)
    {
        const float4* xp = reinterpret_cast<const float4*>(
            x + (size_t)nc * PIX_PER_NC + (size_t)split * CHUNK);
        float4 v0 = xp[tid];
        float4 v1 = xp[tid + 128];
        float4 s0, s1;
        s0.x = fmaf(v0.x, SA2, -SA); s0.y = fmaf(v0.y, SA2, -SA);
        s0.z = fmaf(v0.z, SA2, -SA); s0.w = fmaf(v0.w, SA2, -SA);
        s1.x = fmaf(v1.x, SA2, -SA); s1.y = fmaf(v1.y, SA2, -SA);
        s1.z = fmaf(v1.z, SA2, -SA); s1.w = fmaf(v1.w, SA2, -SA);
        sx[tid]       = s0;
        sx[tid + 128] = s1;
    }

    const float t = SA * bin_vals[bin];            // scaled bin center
    float acc0 = 0.0f, acc1 = 0.0f;

    __syncthreads();

    // Hot loop: group grp walks its 512 pixels; uniform SMEM address -> broadcast.
    const float4* base = sx + grp * (PPG / 4);     // 128 float4
#pragma unroll 8
    for (int i = 0; i < PPG / 4; ++i) {
        float4 s = base[i];
        float d0 = s.x - t;
        float d1 = s.y - t;
        float d2 = s.z - t;
        float d3 = s.w - t;
        acc0 += ex2f(-d0 * d0);
        acc1 += ex2f(-d1 * d1);
        acc0 += ex2f(-d2 * d2);
        acc1 += ex2f(-d3 * d3);
    }

    racc[tid] = acc0 + acc1;
    __syncthreads();

    // Combine the 2 groups, store block partial (no atomics).
    if (tid < HB) {
        g_part[((size_t)nc * SPLITS + split) * HB + tid] = racc[tid] + racc[tid + 64];
    }
    __syncthreads();

    // Last block per nc reduces + normalizes.
    if (tid == 0) {
        __threadfence();
        unsigned old = atomicAdd(&g_cnt[nc], 1u);
        slast = (old == SPLITS - 1);
    }
    __syncthreads();
    if (!slast) return;
    __threadfence();

    float bsum = 0.0f;
    if (tid < HB) {
        const float* p = g_part + (size_t)nc * SPLITS * HB + bin;
#pragma unroll 8
        for (int sp = 0; sp < SPLITS; ++sp)
            bsum += p[(size_t)sp * HB];
    }
    // total over 64 bins (threads 0..63 hold values; all 128 hit barriers)
    float v = (tid < HB) ? bsum : 0.0f;
    float r = v;
#pragma unroll
    for (int o = 16; o; o >>= 1) r += __shfl_xor_sync(0xffffffffu, r, o);
    if (tid == 0)  ws[0] = r;
    if (tid == 32) ws[1] = r;
    __syncthreads();
    float tot = ws[0] + ws[1];

    if (tid < HB)
        out[nc * HB + tid] = v / (tot + 1e-8f);

    if (tid == 0) g_cnt[nc] = 0;   // reset for next graph replay
}

extern "C" void kernel_launch(void* const* d_in, const int* in_sizes, int n_in,
                              void* d_out, int out_size) {
    const float* x        = (const float*)d_in[0];
    const float* bin_vals = (const float*)d_in[1];
    float* out            = (float*)d_out;

    dim3 grid(SPLITS, NC_TOTAL);
    hist_fused_kernel<<<grid, 128>>>(x, bin_vals, out);
}